// round 4
// baseline (speedup 1.0000x reference)
#include <cuda_runtime.h>

#define NP 8192
#define NT 8192
#define CAP 256
#define ROW_F4 (NT/4)

// ---------------- static scratch ----------------
__device__ __align__(16) float d_pa[NP * 64];
__device__ __align__(16) float d_pb[NP * 64];
__device__ __align__(16) float d_ta[NT * 64];
__device__ __align__(16) float d_tb[NT * 64];
__device__ __align__(16) float d_prp[NT * 16];   // t3 @ wp4_agg   (for p-side L4)
__device__ __align__(16) float d_prt[NP * 16];   // p3 @ wt4_agg   (for t-side L4)
__device__ float d_lp[NP];                        // dot(p4, w_ac[0:16])
__device__ float d_logits[NT];
__device__ int d_rcnt[NP];
__device__ int d_ccnt[NT];                        // zero-initialized; re-zeroed each launch at the end
__device__ int d_rlist[NP * CAP];
__device__ int d_clist[NT * CAP];
__device__ unsigned g_arrive = 0;
__device__ volatile unsigned g_gen = 0;

// ---------------- grid-wide barrier (all blocks resident) ----------------
__device__ __forceinline__ void gbar(int nb, unsigned& gen) {
    __syncthreads();
    if (threadIdx.x == 0) {
        __threadfence();
        unsigned a = atomicAdd(&g_arrive, 1u);
        if (a == (unsigned)nb - 1u) {
            atomicExch(&g_arrive, 0u);
            __threadfence();
            g_gen = gen + 1u;
        } else {
            while (g_gen == gen) { __nanosleep(32); }
        }
    }
    gen += 1u;
    __syncthreads();
    __threadfence();
}

// ---------------- per-element emit for build ----------------
__device__ __forceinline__ void emit_edge(int row, int j, int* wcnt) {
    int slot = atomicAdd(wcnt, 1);
    if (slot < CAP) d_rlist[row * CAP + slot] = j;
    int cs = atomicAdd(&d_ccnt[j], 1);
    if (cs < CAP) d_clist[j * CAP + cs] = row;
}
__device__ __forceinline__ void scan_f4(int row, int jb, float4 v, int* wcnt) {
    if (v.x != 0.f || v.y != 0.f || v.z != 0.f || v.w != 0.f) {
        if (v.x != 0.f) emit_edge(row, jb + 0, wcnt);
        if (v.y != 0.f) emit_edge(row, jb + 1, wcnt);
        if (v.z != 0.f) emit_edge(row, jb + 2, wcnt);
        if (v.w != 0.f) emit_edge(row, jb + 3, wcnt);
    }
}

// ---------------- direct layer: out = relu([self|agg] @ W + B) ----------------
template <int IN, int OUT, bool SELF_FIRST>
__device__ __forceinline__ void layer_node(
    int node, const float* __restrict__ self_f, const float* __restrict__ other_f,
    const int* __restrict__ cnt, const int* __restrict__ list,
    const float* sW, const float* sB, float* __restrict__ out_f,
    float* xs, int lane)
{
    constexpr int C = 2 * IN;
    constexpr int SOFF = SELF_FIRST ? 0 : IN;
    constexpr int AOFF = SELF_FIRST ? IN : 0;
#pragma unroll
    for (int k = lane; k < IN; k += 32) xs[SOFF + k] = self_f[node * IN + k];

    constexpr int V = IN / 4;
    constexpr int G = 32 / V;
    int v = lane % V, g = lane / V;
    float4 acc = make_float4(0.f, 0.f, 0.f, 0.f);
    int n = min(cnt[node], CAP);
    const int* lst = list + node * CAP;
    for (int e = g; e < n; e += G) {
        int nbr = lst[e];
        float4 t4 = *reinterpret_cast<const float4*>(other_f + nbr * IN + v * 4);
        acc.x += t4.x; acc.y += t4.y; acc.z += t4.z; acc.w += t4.w;
    }
#pragma unroll
    for (int d = G / 2; d > 0; d >>= 1) {
        acc.x += __shfl_down_sync(0xffffffffu, acc.x, d * V);
        acc.y += __shfl_down_sync(0xffffffffu, acc.y, d * V);
        acc.z += __shfl_down_sync(0xffffffffu, acc.z, d * V);
        acc.w += __shfl_down_sync(0xffffffffu, acc.w, d * V);
    }
    if (g == 0) *reinterpret_cast<float4*>(xs + AOFF + v * 4) = acc;
    __syncwarp();

    constexpr int JPL = (OUT + 31) / 32;
    if (lane < OUT) {
        float a[JPL];
#pragma unroll
        for (int jj = 0; jj < JPL; jj++) a[jj] = sB[lane + jj * 32];
#pragma unroll
        for (int k = 0; k < C; k++) {
            float xv = xs[k];
#pragma unroll
            for (int jj = 0; jj < JPL; jj++) a[jj] += xv * sW[k * OUT + lane + jj * 32];
        }
#pragma unroll
        for (int jj = 0; jj < JPL; jj++)
            out_f[node * OUT + lane + jj * 32] = fmaxf(a[jj], 0.f);
    }
    __syncwarp();
}

// ---------------- layer3 + fused 64->16 projection epilogue ----------------
// Computes y = relu([self|agg] @ W + B) (64-wide), writes it, then proj = y @ Wagg (16-wide).
template <bool SELF_FIRST>
__device__ __forceinline__ void layer3_proj_node(
    int node, const float* __restrict__ self_f, const float* __restrict__ other_f,
    const int* __restrict__ cnt, const int* __restrict__ list,
    const float* sW, const float* sB, const float* sWagg,
    float* __restrict__ out_f, float* __restrict__ proj_f,
    float* xs, int lane)
{
    constexpr int IN = 16, OUT = 64;
    constexpr int SOFF = SELF_FIRST ? 0 : IN;
    constexpr int AOFF = SELF_FIRST ? IN : 0;
#pragma unroll
    for (int k = lane; k < IN; k += 32) xs[SOFF + k] = self_f[node * IN + k];

    int v = lane & 3, g = lane >> 2;   // V=4, G=8
    float4 acc = make_float4(0.f, 0.f, 0.f, 0.f);
    int n = min(cnt[node], CAP);
    const int* lst = list + node * CAP;
    for (int e = g; e < n; e += 8) {
        float4 t4 = *reinterpret_cast<const float4*>(other_f + lst[e] * IN + v * 4);
        acc.x += t4.x; acc.y += t4.y; acc.z += t4.z; acc.w += t4.w;
    }
#pragma unroll
    for (int d = 4; d > 0; d >>= 1) {
        acc.x += __shfl_down_sync(0xffffffffu, acc.x, d * 4);
        acc.y += __shfl_down_sync(0xffffffffu, acc.y, d * 4);
        acc.z += __shfl_down_sync(0xffffffffu, acc.z, d * 4);
        acc.w += __shfl_down_sync(0xffffffffu, acc.w, d * 4);
    }
    if (g == 0) *reinterpret_cast<float4*>(xs + AOFF + v * 4) = acc;
    __syncwarp();

    float a0 = sB[lane], a1 = sB[lane + 32];
#pragma unroll
    for (int k = 0; k < 32; k++) {
        float xv = xs[k];
        a0 += xv * sW[k * OUT + lane];
        a1 += xv * sW[k * OUT + lane + 32];
    }
    a0 = fmaxf(a0, 0.f); a1 = fmaxf(a1, 0.f);
    out_f[node * OUT + lane] = a0;
    out_f[node * OUT + lane + 32] = a1;
    xs[lane] = a0; xs[lane + 32] = a1;          // keep y in smem for the projection
    __syncwarp();

    if (lane < 16) {
        float pr = 0.f;
#pragma unroll
        for (int k = 0; k < 64; k++) pr += xs[k] * sWagg[k * 16 + lane];
        proj_f[node * 16 + lane] = pr;
    }
    __syncwarp();
}

// ---------------- L4 combine: y = relu(self64 @ Wself + sum proj16[nbr] + B); dot w_ac ----------------
__device__ __forceinline__ float l4_node(
    int node, const float* __restrict__ self_f, const float* __restrict__ proj_other,
    const int* __restrict__ cnt, const int* __restrict__ list,
    const float* sWself, const float* sB, const float* sWac,
    float* __restrict__ out_f, float* xs, int lane)
{
#pragma unroll
    for (int k = lane; k < 64; k += 32) xs[k] = self_f[node * 64 + k];

    int v = lane & 3, g = lane >> 2;
    float4 acc = make_float4(0.f, 0.f, 0.f, 0.f);
    int n = min(cnt[node], CAP);
    const int* lst = list + node * CAP;
    for (int e = g; e < n; e += 8) {
        float4 t4 = *reinterpret_cast<const float4*>(proj_other + lst[e] * 16 + v * 4);
        acc.x += t4.x; acc.y += t4.y; acc.z += t4.z; acc.w += t4.w;
    }
#pragma unroll
    for (int d = 4; d > 0; d >>= 1) {
        acc.x += __shfl_down_sync(0xffffffffu, acc.x, d * 4);
        acc.y += __shfl_down_sync(0xffffffffu, acc.y, d * 4);
        acc.z += __shfl_down_sync(0xffffffffu, acc.z, d * 4);
        acc.w += __shfl_down_sync(0xffffffffu, acc.w, d * 4);
    }
    if (g == 0) *reinterpret_cast<float4*>(xs + 64 + v * 4) = acc;
    __syncwarp();

    float contrib = 0.f;
    if (lane < 16) {
        float a = sB[lane] + xs[64 + lane];
#pragma unroll
        for (int k = 0; k < 64; k++) a += xs[k] * sWself[k * 16 + lane];
        float r = fmaxf(a, 0.f);
        out_f[node * 16 + lane] = r;
        contrib = r * sWac[lane];
    }
#pragma unroll
    for (int d = 16; d > 0; d >>= 1)
        contrib += __shfl_down_sync(0xffffffffu, contrib, d);
    __syncwarp();
    return contrib;   // valid in lane 0
}

// ---------------- the single persistent kernel ----------------
__global__ void __launch_bounds__(256) fused_k(
    const float* __restrict__ p0, const float* __restrict__ t0, const float* __restrict__ adj,
    const float* __restrict__ wp1, const float* __restrict__ bp1,
    const float* __restrict__ wt1, const float* __restrict__ bt1,
    const float* __restrict__ wp2, const float* __restrict__ bp2,
    const float* __restrict__ wt2, const float* __restrict__ bt2,
    const float* __restrict__ wp3, const float* __restrict__ bp3,
    const float* __restrict__ wt3, const float* __restrict__ bt3,
    const float* __restrict__ wp4, const float* __restrict__ bp4,
    const float* __restrict__ wt4, const float* __restrict__ bt4,
    const float* __restrict__ wac, const float* __restrict__ bac,
    float* __restrict__ out, int nb)
{
    __shared__ float sWp[2048];
    __shared__ float sWt[2048];
    __shared__ float sWpA[1024];   // wp4 rows 64..127 (agg part, for t3 proj)
    __shared__ float sWtA[1024];   // wt4 rows 0..63  (agg part, for p3 proj)
    __shared__ float sBp[64];
    __shared__ float sBt[64];
    __shared__ float sAC[32];
    __shared__ __align__(16) float sX[8][128];
    __shared__ int s_wcnt[8];
    __shared__ float sRed[256];

    int tid = threadIdx.x, warp = tid >> 5, lane = tid & 31;
    unsigned gen = g_gen;
    int tw = nb * 8;
    int gw = blockIdx.x * 8 + warp;

    // ---- P1: build adjacency lists — one warp per row, streaming, no block syncs ----
    // d_ccnt is all zeros here (static init on first launch, re-zeroed at end of each launch)
    for (int row = gw; row < NP; row += tw) {
        if (lane == 0) s_wcnt[warp] = 0;
        __syncwarp();
        const float4* a4 = reinterpret_cast<const float4*>(adj) + (size_t)row * ROW_F4;
#pragma unroll 1
        for (int base = lane; base < ROW_F4; base += 128) {   // 16 iterations of 4 loads
            float4 v0 = __ldcs(&a4[base]);
            float4 v1 = __ldcs(&a4[base + 32]);
            float4 v2 = __ldcs(&a4[base + 64]);
            float4 v3 = __ldcs(&a4[base + 96]);
            scan_f4(row, (base) << 2,        v0, &s_wcnt[warp]);
            scan_f4(row, (base + 32) << 2,   v1, &s_wcnt[warp]);
            scan_f4(row, (base + 64) << 2,   v2, &s_wcnt[warp]);
            scan_f4(row, (base + 96) << 2,   v3, &s_wcnt[warp]);
        }
        __syncwarp();
        if (lane == 0) d_rcnt[row] = min(s_wcnt[warp], CAP);
        __syncwarp();
    }
    gbar(nb, gen);

    // ---- P2: layer 1 (8,8)->(8,8) ----
    for (int i = tid; i < 128; i += 256) { sWp[i] = wp1[i]; sWt[i] = wt1[i]; }
    if (tid < 8) { sBp[tid] = bp1[tid]; sBt[tid] = bt1[tid]; }
    __syncthreads();
    for (int idx = gw; idx < NP + NT; idx += tw) {
        if (idx < NP) layer_node<8, 8, true >(idx,      p0, t0, d_rcnt, d_rlist, sWp, sBp, d_pa, sX[warp], lane);
        else          layer_node<8, 8, false>(idx - NP, t0, p0, d_ccnt, d_clist, sWt, sBt, d_ta, sX[warp], lane);
    }
    gbar(nb, gen);

    // ---- P3: layer 2 (8,8)->(16,16) ----
    for (int i = tid; i < 256; i += 256) { sWp[i] = wp2[i]; sWt[i] = wt2[i]; }
    if (tid < 16) { sBp[tid] = bp2[tid]; sBt[tid] = bt2[tid]; }
    __syncthreads();
    for (int idx = gw; idx < NP + NT; idx += tw) {
        if (idx < NP) layer_node<8, 16, true >(idx,      d_pa, d_ta, d_rcnt, d_rlist, sWp, sBp, d_pb, sX[warp], lane);
        else          layer_node<8, 16, false>(idx - NP, d_ta, d_pa, d_ccnt, d_clist, sWt, sBt, d_tb, sX[warp], lane);
    }
    gbar(nb, gen);

    // ---- P4: layer 3 (16,16)->(64,64)  +  fused 64->16 projection epilogue ----
    for (int i = tid; i < 2048; i += 256) { sWp[i] = wp3[i]; sWt[i] = wt3[i]; }
    for (int i = tid; i < 1024; i += 256) { sWpA[i] = wp4[1024 + i]; sWtA[i] = wt4[i]; }
    if (tid < 64) { sBp[tid] = bp3[tid]; sBt[tid] = bt3[tid]; }
    __syncthreads();
    for (int idx = gw; idx < NP + NT; idx += tw) {
        if (idx < NP) layer3_proj_node<true >(idx,      d_pb, d_tb, d_rcnt, d_rlist, sWp, sBp, sWtA, d_pa, d_prt, sX[warp], lane);
        else          layer3_proj_node<false>(idx - NP, d_tb, d_pb, d_ccnt, d_clist, sWt, sBt, sWpA, d_ta, d_prp, sX[warp], lane);
    }
    gbar(nb, gen);

    // ---- P5: p-side L4 combine -> d_lp ----
    for (int i = tid; i < 1024; i += 256) { sWp[i] = wp4[i]; sWt[i] = wt4[1024 + i]; }  // self parts
    if (tid < 16) { sBp[tid] = bp4[tid]; sBt[tid] = bt4[tid]; }
    if (tid < 32) sAC[tid] = wac[tid];
    __syncthreads();
    for (int idx = gw; idx < NP; idx += tw) {
        float c = l4_node(idx, d_pa, d_prp, d_rcnt, d_rlist, sWp, sBp, sAC, d_pb, sX[warp], lane);
        if (lane == 0) d_lp[idx] = c;
    }
    gbar(nb, gen);

    // ---- P6: t-side L4 combine + logits (gather d_lp over columns) ----
    {
        float bias = bac[0];
        for (int idx = gw; idx < NT; idx += tw) {
            float c = l4_node(idx, d_ta, d_prt, d_ccnt, d_clist, sWt, sBt, sAC + 16, d_tb, sX[warp], lane);
            int n = min(d_ccnt[idx], CAP);
            const int* lst = d_clist + idx * CAP;
            float s = 0.f;
            for (int e = lane; e < n; e += 32) s += d_lp[lst[e]];
#pragma unroll
            for (int d = 16; d > 0; d >>= 1) s += __shfl_down_sync(0xffffffffu, s, d);
            if (lane == 0) d_logits[idx] = s + c + bias;
        }
    }
    gbar(nb, gen);

    // ---- P7: redundant softmax reduction per block + write + re-zero ccnt ----
    {
        float m = -1e30f;
        for (int i = tid; i < NT; i += 256) m = fmaxf(m, d_logits[i]);
        sRed[tid] = m; __syncthreads();
        for (int s = 128; s > 0; s >>= 1) {
            if (tid < s) sRed[tid] = fmaxf(sRed[tid], sRed[tid + s]);
            __syncthreads();
        }
        float mx = sRed[0]; __syncthreads();
        float sum = 0.f;
        for (int i = tid; i < NT; i += 256) sum += __expf(d_logits[i] - mx);
        sRed[tid] = sum; __syncthreads();
        for (int s = 128; s > 0; s >>= 1) {
            if (tid < s) sRed[tid] += sRed[tid + s];
            __syncthreads();
        }
        float inv = 1.f / sRed[0];
        for (int i = blockIdx.x * 256 + tid; i < NT; i += nb * 256) {
            out[i] = __expf(d_logits[i] - mx) * inv;
            d_ccnt[i] = 0;     // reset for the next launch
        }
    }
}

// ---------------- launch ----------------
extern "C" void kernel_launch(void* const* d_in, const int* in_sizes, int n_in,
                              void* d_out, int out_size) {
    const float* p    = (const float*)d_in[0];
    const float* t    = (const float*)d_in[1];
    const float* adj  = (const float*)d_in[2];
    const float* w_p1 = (const float*)d_in[3];  const float* b_p1 = (const float*)d_in[4];
    const float* w_t1 = (const float*)d_in[5];  const float* b_t1 = (const float*)d_in[6];
    const float* w_p2 = (const float*)d_in[7];  const float* b_p2 = (const float*)d_in[8];
    const float* w_t2 = (const float*)d_in[9];  const float* b_t2 = (const float*)d_in[10];
    const float* w_p3 = (const float*)d_in[11]; const float* b_p3 = (const float*)d_in[12];
    const float* w_t3 = (const float*)d_in[13]; const float* b_t3 = (const float*)d_in[14];
    const float* w_p4 = (const float*)d_in[15]; const float* b_p4 = (const float*)d_in[16];
    const float* w_t4 = (const float*)d_in[17]; const float* b_t4 = (const float*)d_in[18];
    const float* w_ac = (const float*)d_in[19]; const float* b_ac = (const float*)d_in[20];
    float* out = (float*)d_out;

    int dev = 0;
    cudaGetDevice(&dev);
    int sms = 0;
    cudaDeviceGetAttribute(&sms, cudaDevAttrMultiProcessorCount, dev);
    int bpm = 0;
    cudaOccupancyMaxActiveBlocksPerMultiprocessor(&bpm, fused_k, 256, 0);
    if (bpm < 1) bpm = 1;
    if (bpm > 6) bpm = 6;          // cheaper grid barriers; enough warps for DRAM saturation
    int nb = sms * bpm;
    if (nb > NP) nb = NP;

    fused_k<<<nb, 256>>>(p, t, adj,
                         w_p1, b_p1, w_t1, b_t1,
                         w_p2, b_p2, w_t2, b_t2,
                         w_p3, b_p3, w_t3, b_t3,
                         w_p4, b_p4, w_t4, b_t4,
                         w_ac, b_ac, out, nb);
}